// round 6
// baseline (speedup 1.0000x reference)
#include <cuda_runtime.h>
#include <stdint.h>

#define NUM_OBJ_CLS 151
#define NUM_REL_CLS 51

// ---------------------------------------------------------------------------
// obj_dists = exact one-hot (softmax of +/-1000 fp32 logits underflows).
// One float4 of the [n_obj, 151] block per thread.
// ---------------------------------------------------------------------------
__global__ void onehot_kernel(const int* __restrict__ labels,
                              float* __restrict__ out,
                              int n_floats) {
    int i = blockIdx.x * blockDim.x + threadIdx.x;
    int f0 = i * 4;
    if (f0 >= n_floats) return;

    if (f0 + 3 < n_floats) {
        float4 v;
        #pragma unroll
        for (int k = 0; k < 4; k++) {
            int f = f0 + k;
            int r = f / NUM_OBJ_CLS, c = f - r * NUM_OBJ_CLS;
            float val = (__ldg(&labels[r]) == c) ? 1.0f : 0.0f;
            if (k == 0) v.x = val; else if (k == 1) v.y = val;
            else if (k == 2) v.z = val; else v.w = val;
        }
        *(float4*)(out + f0) = v;
    } else {
        for (int f = f0; f < n_floats; f++) {
            int r = f / NUM_OBJ_CLS, c = f - r * NUM_OBJ_CLS;
            out[f] = (__ldg(&labels[r]) == c) ? 1.0f : 0.0f;
        }
    }
}

// ---------------------------------------------------------------------------
// rel_dists: warp handles 32 pairs = 1632 output floats = exactly 51
// warp-wide stride-1 iterations. Load index space == store index space, so
// no staging is needed: lane reads chunk-float f = k*32+lane from
// table[b(j)+c] (row base via shfl) and stores it straight to
// out[chunk_base + f]. Both sides are dense 128B wavefronts (chunk base is
// 128B-aligned: 32*204 = 51*128). (j,c) advance incrementally: c += 32,
// wrap at 51 -> j += 1 (32 < 51 so j steps by at most 1).
// ---------------------------------------------------------------------------
__global__ void __launch_bounds__(256)
rel_gather_kernel(const int* __restrict__ labels,
                  const int2* __restrict__ pairs,
                  const float* __restrict__ table,
                  float* __restrict__ out,
                  int n_pairs) {
    const int lane = threadIdx.x & 31;
    const int warp_id   = (blockIdx.x * blockDim.x + threadIdx.x) >> 5;
    const int num_warps = (gridDim.x * blockDim.x) >> 5;
    const int n_chunks  = n_pairs >> 5;

    for (int chunk = warp_id; chunk < n_chunks; chunk += num_warps) {
        const int p0 = chunk << 5;

        // Per-lane index resolution: 32 independent dependent-load chains.
        int2 pr = __ldg(&pairs[p0 + lane]);
        int h = __ldg(&labels[pr.x]);
        int t = __ldg(&labels[pr.y]);
        int base = (h * NUM_OBJ_CLS + t) * NUM_REL_CLS;

        float* __restrict__ dst = out + (size_t)p0 * NUM_REL_CLS;

        // f = k*32 + lane; j = f / 51, c = f % 51, maintained incrementally.
        int j = 0;          // lane < 32 <= 50, so j starts at 0
        int c = lane;
        #pragma unroll
        for (int k = 0; k < NUM_REL_CLS; k++) {
            int b = __shfl_sync(0xffffffffu, base, j);
            float v = __ldg(table + b + c);
            __stcs(dst + k * 32 + lane, v);
            c += 32;
            if (c >= NUM_REL_CLS) { c -= NUM_REL_CLS; j += 1; }
        }
    }

    // Leftover pairs (n_pairs % 32): absent for 2M pairs, kept for generality.
    if (warp_id == 0) {
        for (int p = n_chunks << 5; p < n_pairs; p++) {
            int2 pr = __ldg(&pairs[p]);
            int h = __ldg(&labels[pr.x]);
            int t = __ldg(&labels[pr.y]);
            int b = (h * NUM_OBJ_CLS + t) * NUM_REL_CLS;
            float* __restrict__ dstp = out + (size_t)p * NUM_REL_CLS;
            if (lane < NUM_REL_CLS) dstp[lane] = __ldg(table + b + lane);
            if (lane < NUM_REL_CLS - 32) dstp[32 + lane] = __ldg(table + b + 32 + lane);
        }
    }
}

extern "C" void kernel_launch(void* const* d_in, const int* in_sizes, int n_in,
                              void* d_out, int out_size) {
    const int*   labels = (const int*)d_in[0];          // [N_OBJ] int32
    const int2*  pairs  = (const int2*)d_in[1];         // [N_PAIRS, 2] int32
    const float* table  = (const float*)d_in[2];        // [151,151,51] f32

    const int n_obj   = in_sizes[0];
    const int n_pairs = in_sizes[1] / 2;

    float* obj_out = (float*)d_out;                               // [n_obj, 151]
    float* rel_out = obj_out + (size_t)n_obj * NUM_OBJ_CLS;       // [n_pairs, 51]

    // obj_dists
    int n_obj_floats = n_obj * NUM_OBJ_CLS;
    int n_vec = (n_obj_floats + 3) / 4;
    onehot_kernel<<<(n_vec + 255) / 256, 256>>>(labels, obj_out, n_obj_floats);

    // rel_dists: 2048 blocks x 256 thr = 16384 warps, ~3.8 chunks each.
    rel_gather_kernel<<<2048, 256>>>(labels, pairs, table, rel_out, n_pairs);
}

// round 7
// speedup vs baseline: 1.3408x; 1.3408x over previous
#include <cuda_runtime.h>
#include <stdint.h>

#define NUM_OBJ_CLS 151
#define NUM_REL_CLS 51

// ---------------------------------------------------------------------------
// obj_dists = exact one-hot (softmax of +/-1000 fp32 logits underflows).
// One float4 of the [n_obj, 151] block per thread.
// ---------------------------------------------------------------------------
__global__ void onehot_kernel(const int* __restrict__ labels,
                              float* __restrict__ out,
                              int n_floats) {
    int i = blockIdx.x * blockDim.x + threadIdx.x;
    int f0 = i * 4;
    if (f0 >= n_floats) return;

    if (f0 + 3 < n_floats) {
        float4 v;
        #pragma unroll
        for (int k = 0; k < 4; k++) {
            int f = f0 + k;
            int r = f / NUM_OBJ_CLS, c = f - r * NUM_OBJ_CLS;
            float val = (__ldg(&labels[r]) == c) ? 1.0f : 0.0f;
            if (k == 0) v.x = val; else if (k == 1) v.y = val;
            else if (k == 2) v.z = val; else v.w = val;
        }
        *(float4*)(out + f0) = v;
    } else {
        for (int f = f0; f < n_floats; f++) {
            int r = f / NUM_OBJ_CLS, c = f - r * NUM_OBJ_CLS;
            out[f] = (__ldg(&labels[r]) == c) ? 1.0f : 0.0f;
        }
    }
}

// ---------------------------------------------------------------------------
// rel_dists: warp handles 32 pairs = 1632 output floats = exactly 51
// warp-wide stride-1 iterations. Load index space == store index space:
// lane reads chunk-float f = k*32+lane from table[b(j)+c] (row base via
// shfl, j = f/51, c = f%51 maintained incrementally) and stores directly
// to out[chunk_base + f]. Both sides are dense 128B wavefronts.
// unroll 3 (51 = 3*17) keeps 3 loads in flight without register blowup
// (R6 lesson: full unroll -> 198 regs -> 12% occupancy).
// ---------------------------------------------------------------------------
__global__ void __launch_bounds__(256, 8)
rel_gather_kernel(const int* __restrict__ labels,
                  const int2* __restrict__ pairs,
                  const float* __restrict__ table,
                  float* __restrict__ out,
                  int n_pairs) {
    const int lane = threadIdx.x & 31;
    const int warp_id   = (blockIdx.x * blockDim.x + threadIdx.x) >> 5;
    const int num_warps = (gridDim.x * blockDim.x) >> 5;
    const int n_chunks  = n_pairs >> 5;

    for (int chunk = warp_id; chunk < n_chunks; chunk += num_warps) {
        const int p0 = chunk << 5;

        // Per-lane index resolution: 32 independent dependent-load chains.
        int2 pr = __ldg(&pairs[p0 + lane]);
        int h = __ldg(&labels[pr.x]);
        int t = __ldg(&labels[pr.y]);
        int base = (h * NUM_OBJ_CLS + t) * NUM_REL_CLS;

        float* __restrict__ dst = out + (size_t)p0 * NUM_REL_CLS;

        // f = k*32 + lane; j = f/51, c = f%51, incrementally maintained.
        int j = 0;            // lane < 32 <= 50 -> j starts at 0
        int c = lane;
        #pragma unroll 3
        for (int k = 0; k < NUM_REL_CLS; k++) {
            int b = __shfl_sync(0xffffffffu, base, j);
            float v = __ldg(table + b + c);
            __stcs(dst + k * 32 + lane, v);
            c += 32;
            if (c >= NUM_REL_CLS) { c -= NUM_REL_CLS; j += 1; }
        }
    }

    // Leftover pairs (n_pairs % 32): absent for 2M pairs, kept for generality.
    if (warp_id == 0) {
        for (int p = n_chunks << 5; p < n_pairs; p++) {
            int2 pr = __ldg(&pairs[p]);
            int h = __ldg(&labels[pr.x]);
            int t = __ldg(&labels[pr.y]);
            int b = (h * NUM_OBJ_CLS + t) * NUM_REL_CLS;
            float* __restrict__ dstp = out + (size_t)p * NUM_REL_CLS;
            if (lane < NUM_REL_CLS) dstp[lane] = __ldg(table + b + lane);
            if (lane < NUM_REL_CLS - 32) dstp[32 + lane] = __ldg(table + b + 32 + lane);
        }
    }
}

extern "C" void kernel_launch(void* const* d_in, const int* in_sizes, int n_in,
                              void* d_out, int out_size) {
    const int*   labels = (const int*)d_in[0];          // [N_OBJ] int32
    const int2*  pairs  = (const int2*)d_in[1];         // [N_PAIRS, 2] int32
    const float* table  = (const float*)d_in[2];        // [151,151,51] f32

    const int n_obj   = in_sizes[0];
    const int n_pairs = in_sizes[1] / 2;

    float* obj_out = (float*)d_out;                               // [n_obj, 151]
    float* rel_out = obj_out + (size_t)n_obj * NUM_OBJ_CLS;       // [n_pairs, 51]

    // obj_dists
    int n_obj_floats = n_obj * NUM_OBJ_CLS;
    int n_vec = (n_obj_floats + 3) / 4;
    onehot_kernel<<<(n_vec + 255) / 256, 256>>>(labels, obj_out, n_obj_floats);

    // rel_dists: 2048 blocks x 256 thr = 16384 warps, ~3.8 chunks each.
    rel_gather_kernel<<<2048, 256>>>(labels, pairs, table, rel_out, n_pairs);
}

// round 8
// speedup vs baseline: 1.4460x; 1.0785x over previous
#include <cuda_runtime.h>
#include <stdint.h>

#define NUM_OBJ_CLS 151
#define NUM_REL_CLS 51

// ---------------------------------------------------------------------------
// Fused kernel.
// Section 1 (obj_dists): exact one-hot (softmax of +/-1000 fp32 logits
//   underflows to one-hot). Grid-stride over float4s of the [n_obj,151] block.
// Section 2 (rel_dists): warp handles 32 pairs = 1632 output floats =
//   exactly 51 warp-wide stride-1 iterations. Load index space == store
//   index space: lane reads chunk-float f = k*32+lane from table[b(j)+c]
//   (j = f/51 via constant-divisor mulhi -> iterations fully independent,
//   row base via shfl) and stores directly to out[chunk_base+f]. Both sides
//   are dense 128B wavefronts (chunk base 128B-aligned: 32*204 = 51*128).
// ---------------------------------------------------------------------------
__global__ void __launch_bounds__(256, 8)
fused_kernel(const int* __restrict__ labels,
             const int2* __restrict__ pairs,
             const float* __restrict__ table,
             float* __restrict__ obj_out,
             float* __restrict__ rel_out,
             int n_obj, int n_pairs) {
    const int tid_global = blockIdx.x * blockDim.x + threadIdx.x;
    const int n_threads  = gridDim.x * blockDim.x;

    // ---- Section 1: one-hot (n_obj*151 floats; divisible by 4 when
    //      n_obj is even; general tail handled scalar by thread 0). ----
    {
        const int n_floats = n_obj * NUM_OBJ_CLS;
        const int n_vec = n_floats >> 2;
        for (int i = tid_global; i < n_vec; i += n_threads) {
            int f0 = i * 4;
            float4 v;
            #pragma unroll
            for (int k = 0; k < 4; k++) {
                int f = f0 + k;
                int r = f / NUM_OBJ_CLS, c = f - r * NUM_OBJ_CLS;
                float val = (__ldg(&labels[r]) == c) ? 1.0f : 0.0f;
                if (k == 0) v.x = val; else if (k == 1) v.y = val;
                else if (k == 2) v.z = val; else v.w = val;
            }
            *(float4*)(obj_out + f0) = v;
        }
        if (tid_global == 0) {
            for (int f = n_vec * 4; f < n_floats; f++) {
                int r = f / NUM_OBJ_CLS, c = f - r * NUM_OBJ_CLS;
                obj_out[f] = (__ldg(&labels[r]) == c) ? 1.0f : 0.0f;
            }
        }
    }

    // ---- Section 2: rel gather. ----
    const int lane = threadIdx.x & 31;
    const int warp_id   = tid_global >> 5;
    const int num_warps = n_threads >> 5;
    const int n_chunks  = n_pairs >> 5;

    for (int chunk = warp_id; chunk < n_chunks; chunk += num_warps) {
        const int p0 = chunk << 5;

        // Per-lane index resolution: 32 independent pair->label->base chains.
        int2 pr = __ldg(&pairs[p0 + lane]);
        int h = __ldg(&labels[pr.x]);
        int t = __ldg(&labels[pr.y]);
        int base = (h * NUM_OBJ_CLS + t) * NUM_REL_CLS;

        float* __restrict__ dst = rel_out + (size_t)p0 * NUM_REL_CLS;

        // 51 independent iterations: j,c from k via constant division
        // (mulhi), so ptxas can pipeline loads freely (R7 lesson: the
        // incremental j,c chain serialized the loop; R6 lesson: full
        // unroll blows registers -> cap at 51 iterations, unroll 6).
        #pragma unroll 6
        for (int k = 0; k < NUM_REL_CLS; k++) {
            int f = k * 32 + lane;
            int j = f / NUM_REL_CLS;           // mulhi with magic constant
            int c = f - j * NUM_REL_CLS;
            int b = __shfl_sync(0xffffffffu, base, j);
            float v = __ldg(table + b + c);
            __stcs(dst + f, v);
        }
    }

    // Leftover pairs (n_pairs % 32): absent for 2M pairs, kept for generality.
    if (warp_id == 0) {
        for (int p = n_chunks << 5; p < n_pairs; p++) {
            int2 pr = __ldg(&pairs[p]);
            int h = __ldg(&labels[pr.x]);
            int t = __ldg(&labels[pr.y]);
            int b = (h * NUM_OBJ_CLS + t) * NUM_REL_CLS;
            float* __restrict__ dstp = rel_out + (size_t)p * NUM_REL_CLS;
            if (lane < NUM_REL_CLS) dstp[lane] = __ldg(table + b + lane);
            if (lane < NUM_REL_CLS - 32) dstp[32 + lane] = __ldg(table + b + 32 + lane);
        }
    }
}

extern "C" void kernel_launch(void* const* d_in, const int* in_sizes, int n_in,
                              void* d_out, int out_size) {
    const int*   labels = (const int*)d_in[0];          // [N_OBJ] int32
    const int2*  pairs  = (const int2*)d_in[1];         // [N_PAIRS, 2] int32
    const float* table  = (const float*)d_in[2];        // [151,151,51] f32

    const int n_obj   = in_sizes[0];
    const int n_pairs = in_sizes[1] / 2;

    float* obj_out = (float*)d_out;                               // [n_obj, 151]
    float* rel_out = obj_out + (size_t)n_obj * NUM_OBJ_CLS;       // [n_pairs, 51]

    fused_kernel<<<2048, 256>>>(labels, pairs, table, obj_out, rel_out,
                                n_obj, n_pairs);
}